// round 4
// baseline (speedup 1.0000x reference)
#include <cuda_runtime.h>
#include <cuda_fp16.h>
#include <cstdint>

// ---------------------------------------------------------------------------
// out[8192,4096] = x[8192,4096]_fp32 @ sign(fp16(w[4096,4096]))
//
// Portable tensor-core path (target is plain sm_103): cp.async + ldmatrix +
// mma.sync.m16n8k16.f32.f16.f16.f32.
//
// R4: CTA tile 128x256, warp tile 64x64 (8 warps 2x4) -> 1.5x FLOP per smem
// byte; smem crossbar (1408 cyc/iter) drops below MMA pipe (2048 cyc/iter).
// 3-stage cp.async ring (144 KB).
// ---------------------------------------------------------------------------

#define M_DIM 8192
#define N_DIM 4096
#define K_DIM 4096

#define BM 128
#define BN 256
#define BK 64
#define STAGES 3
#define THREADS 256
#define NKI (K_DIM / BK)   // 64

#define A_TILE_BYTES (BM * BK * 2)            // 16384
#define B_TILE_BYTES (BN * BK * 2)            // 32768
#define STAGE_BYTES  (A_TILE_BYTES + B_TILE_BYTES)   // 49152
#define SMEM_DYN     (STAGES * STAGE_BYTES)          // 147456

// ------------------------------ scratch -----------------------------------
__device__ __align__(1024) __half g_xh[(size_t)M_DIM * K_DIM];   // 64 MB
__device__ __align__(1024) __half g_wbt[(size_t)N_DIM * K_DIM];  // 32 MB

// --------------------------- convert kernels -------------------------------
__global__ void cvt_x_kernel(const float4* __restrict__ x, uint2* __restrict__ xh, int n4) {
    int i = blockIdx.x * blockDim.x + threadIdx.x;
    if (i >= n4) return;
    float4 v = x[i];
    __half2 a = __floats2half2_rn(v.x, v.y);
    __half2 b = __floats2half2_rn(v.z, v.w);
    uint2 o;
    o.x = *reinterpret_cast<uint32_t*>(&a);
    o.y = *reinterpret_cast<uint32_t*>(&b);
    xh[i] = o;
}

// w[K,N] fp32 -> wbt[N,K] fp16 with value sign(fp16(w)) (sign(0) = 0)
__global__ void cvt_w_kernel(const float* __restrict__ w, __half* __restrict__ wbt) {
    __shared__ __half tile[32][33];
    int n0 = blockIdx.x * 32;
    int k0 = blockIdx.y * 32;
    int tx = threadIdx.x, ty = threadIdx.y;
    #pragma unroll
    for (int j = ty; j < 32; j += 8) {
        float v = w[(size_t)(k0 + j) * N_DIM + n0 + tx];
        float hf = __half2float(__float2half_rn(v));  // exact fp16 round trip
        float s = (hf > 0.f) ? 1.f : ((hf < 0.f) ? -1.f : 0.f);
        tile[j][tx] = __float2half_rn(s);
    }
    __syncthreads();
    #pragma unroll
    for (int j = ty; j < 32; j += 8) {
        wbt[(size_t)(n0 + j) * K_DIM + k0 + tx] = tile[tx][j];
    }
}

// dummy launch to shift ncu's -s window onto the GEMM
__global__ void prof_pad_kernel() {}

// ------------------------------ PTX helpers -------------------------------
__device__ __forceinline__ uint32_t smem_u32(const void* p) {
    uint32_t a;
    asm("{ .reg .u64 t; cvta.to.shared.u64 t, %1; cvt.u32.u64 %0, t; }"
        : "=r"(a) : "l"(p));
    return a;
}

__device__ __forceinline__ void cp_async_16(uint32_t smem_dst, const void* gmem_src) {
    asm volatile("cp.async.cg.shared.global [%0], [%1], 16;"
                 :: "r"(smem_dst), "l"(gmem_src));
}
__device__ __forceinline__ void cp_commit() {
    asm volatile("cp.async.commit_group;" ::: "memory");
}
template <int N>
__device__ __forceinline__ void cp_wait() {
    asm volatile("cp.async.wait_group %0;" :: "n"(N) : "memory");
}

__device__ __forceinline__ void ldmatrix_x4(uint32_t& r0, uint32_t& r1,
                                            uint32_t& r2, uint32_t& r3, uint32_t addr) {
    asm volatile("ldmatrix.sync.aligned.m8n8.x4.shared.b16 {%0,%1,%2,%3}, [%4];"
                 : "=r"(r0), "=r"(r1), "=r"(r2), "=r"(r3) : "r"(addr));
}

__device__ __forceinline__ void mma_16816(float* c, const uint32_t* a, const uint32_t* b) {
    asm volatile(
        "mma.sync.aligned.m16n8k16.row.col.f32.f16.f16.f32 "
        "{%0,%1,%2,%3}, {%4,%5,%6,%7}, {%8,%9}, {%0,%1,%2,%3};"
        : "+f"(c[0]), "+f"(c[1]), "+f"(c[2]), "+f"(c[3])
        : "r"(a[0]), "r"(a[1]), "r"(a[2]), "r"(a[3]), "r"(b[0]), "r"(b[1]));
}

// swizzle within a [rows][BK] fp16 tile, 128B rows: 16B chunk XOR (row & 7)
__device__ __forceinline__ uint32_t tile_off(int row, int chunk) {
    return (uint32_t)(row * 128 + ((chunk ^ (row & 7)) << 4));
}

// ------------------------------ GEMM kernel --------------------------------
__global__ void __launch_bounds__(THREADS, 1) bgemm_mma_kernel(
    const __half* __restrict__ A,   // [M,K]
    const __half* __restrict__ B,   // [N,K]
    float* __restrict__ out)
{
    extern __shared__ uint8_t smem_raw[];
    const uint32_t smem = smem_u32(smem_raw);

    const int tid  = threadIdx.x;
    const int wid  = tid >> 5;
    const int lane = tid & 31;
    const int m0 = blockIdx.x * BM;
    const int n0 = blockIdx.y * BN;

    const int warp_m = wid & 1;   // 2 warps over M: 64 rows each
    const int warp_n = wid >> 1;  // 4 warps over N: 64 cols each

    // cp.async mapping: 256 threads x 16B. A: 128 rows x 8 chunks (4 passes),
    // B: 256 rows x 8 chunks (8 passes).
    const int ld_row0  = tid >> 3;   // 0..31
    const int ld_chunk = tid & 7;    // 0..7

    auto load_stage = [&](int slot, int kt) {
        const uint32_t sA = smem + slot * STAGE_BYTES;
        const uint32_t sB = sA + A_TILE_BYTES;
        const int kcol = kt * BK + ld_chunk * 8;
        #pragma unroll
        for (int p = 0; p < 4; p++) {
            int row = ld_row0 + p * 32;
            cp_async_16(sA + tile_off(row, ld_chunk),
                        A + (size_t)(m0 + row) * K_DIM + kcol);
        }
        #pragma unroll
        for (int p = 0; p < 8; p++) {
            int row = ld_row0 + p * 32;
            cp_async_16(sB + tile_off(row, ld_chunk),
                        B + (size_t)(n0 + row) * K_DIM + kcol);
        }
        cp_commit();
    };

    const int lrow = lane & 15;    // ldmatrix row within 16
    const int lsel = lane >> 4;    // ldmatrix chunk select (0/1)

    float acc[4][8][4];
    #pragma unroll
    for (int mi = 0; mi < 4; mi++)
        #pragma unroll
        for (int ni = 0; ni < 8; ni++)
            #pragma unroll
            for (int j = 0; j < 4; j++) acc[mi][ni][j] = 0.f;

    // prologue: fill stages 0..1
    #pragma unroll
    for (int s = 0; s < STAGES - 1; s++) load_stage(s, s);

    for (int it = 0; it < NKI; it++) {
        cp_wait<STAGES - 2>();   // stage it resident
        __syncthreads();         // all warps done reading slot (it-1)%3

        if (it + STAGES - 1 < NKI)
            load_stage((it + STAGES - 1) % STAGES, it + STAGES - 1);

        const uint32_t sA = smem + (it % STAGES) * STAGE_BYTES;
        const uint32_t sB = sA + A_TILE_BYTES;

        #pragma unroll
        for (int kk = 0; kk < BK / 16; kk++) {
            const int chunk = kk * 2 + lsel;

            uint32_t a[4][4];
            #pragma unroll
            for (int mi = 0; mi < 4; mi++) {
                int row = warp_m * 64 + mi * 16 + lrow;
                ldmatrix_x4(a[mi][0], a[mi][1], a[mi][2], a[mi][3],
                            sA + tile_off(row, chunk));
            }
            uint32_t b[8][2];
            #pragma unroll
            for (int nj = 0; nj < 4; nj++) {
                int row = warp_n * 64 + nj * 16 + lrow;
                uint32_t r0, r1, r2, r3;
                ldmatrix_x4(r0, r1, r2, r3, sB + tile_off(row, chunk));
                b[nj * 2 + 0][0] = r0; b[nj * 2 + 1][0] = r1;
                b[nj * 2 + 0][1] = r2; b[nj * 2 + 1][1] = r3;
            }
            #pragma unroll
            for (int mi = 0; mi < 4; mi++)
                #pragma unroll
                for (int ni = 0; ni < 8; ni++)
                    mma_16816(acc[mi][ni], a[mi], b[ni]);
        }
    }

    // ------------------------------ epilogue -------------------------------
    const int tq = lane >> 2;       // 0..7 (row within 8)
    const int tp = lane & 3;        // col pair
    #pragma unroll
    for (int mi = 0; mi < 4; mi++) {
        #pragma unroll
        for (int ni = 0; ni < 8; ni++) {
            int r = m0 + warp_m * 64 + mi * 16 + tq;
            int c = n0 + warp_n * 64 + ni * 8 + tp * 2;
            float2 v0 = make_float2(acc[mi][ni][0], acc[mi][ni][1]);
            float2 v1 = make_float2(acc[mi][ni][2], acc[mi][ni][3]);
            *reinterpret_cast<float2*>(out + (size_t)r * N_DIM + c) = v0;
            *reinterpret_cast<float2*>(out + (size_t)(r + 8) * N_DIM + c) = v1;
        }
    }
}

// ------------------------------- host side --------------------------------
extern "C" void kernel_launch(void* const* d_in, const int* in_sizes, int n_in,
                              void* d_out, int out_size)
{
    const float* x = (const float*)d_in[0];
    const float* w = (const float*)d_in[1];
    float* out = (float*)d_out;

    void *xh_ptr = nullptr, *wbt_ptr = nullptr;
    cudaGetSymbolAddress(&xh_ptr, g_xh);
    cudaGetSymbolAddress(&wbt_ptr, g_wbt);

    {
        int n4 = (M_DIM * K_DIM) / 4;
        cvt_x_kernel<<<(n4 + 255) / 256, 256>>>((const float4*)x, (uint2*)xh_ptr, n4);
        dim3 gw(N_DIM / 32, K_DIM / 32), bw(32, 8);
        cvt_w_kernel<<<gw, bw>>>(w, (__half*)wbt_ptr);
    }

    // pad launch so ncu's "-s 5 -c 1" window lands on the GEMM (period 4,
    // GEMM at position 3; observed offset puts index 5 at position 3)
    prof_pad_kernel<<<1, 32>>>();

    cudaFuncSetAttribute(bgemm_mma_kernel,
                         cudaFuncAttributeMaxDynamicSharedMemorySize, SMEM_DYN);

    dim3 grid(M_DIM / BM, N_DIM / BN);  // (64, 16)
    bgemm_mma_kernel<<<grid, THREADS, SMEM_DYN>>>(
        (const __half*)xh_ptr, (const __half*)wbt_ptr, out);
}

// round 5
// speedup vs baseline: 1.0173x; 1.0173x over previous
#include <cuda_runtime.h>
#include <cuda_fp16.h>
#include <cstdint>

// ---------------------------------------------------------------------------
// out[8192,4096] = x[8192,4096]_fp32 @ sign(fp16(w[4096,4096]))
//
// Portable tensor-core path (target is plain sm_103): cp.async + ldmatrix +
// mma.sync.m16n8k16.f32.f16.f16.f32.
//
// R5: CTA tile 128x256 with 512 threads (16 warps, warp tile 32x64, 4Mx4N).
// Doubles warps per SMSP (2 -> 4) to hide LDSM latency; tensor pipe was 61%
// busy at occ=12.5% purely from latency bubbles.
// ---------------------------------------------------------------------------

#define M_DIM 8192
#define N_DIM 4096
#define K_DIM 4096

#define BM 128
#define BN 256
#define BK 64
#define STAGES 3
#define THREADS 512
#define NKI (K_DIM / BK)   // 64

#define A_TILE_BYTES (BM * BK * 2)            // 16384
#define B_TILE_BYTES (BN * BK * 2)            // 32768
#define STAGE_BYTES  (A_TILE_BYTES + B_TILE_BYTES)   // 49152
#define SMEM_DYN     (STAGES * STAGE_BYTES)          // 147456

// ------------------------------ scratch -----------------------------------
__device__ __align__(1024) __half g_xh[(size_t)M_DIM * K_DIM];   // 64 MB
__device__ __align__(1024) __half g_wbt[(size_t)N_DIM * K_DIM];  // 32 MB

// --------------------------- convert kernels -------------------------------
__global__ void cvt_x_kernel(const float4* __restrict__ x, uint2* __restrict__ xh, int n4) {
    int i = blockIdx.x * blockDim.x + threadIdx.x;
    if (i >= n4) return;
    float4 v = x[i];
    __half2 a = __floats2half2_rn(v.x, v.y);
    __half2 b = __floats2half2_rn(v.z, v.w);
    uint2 o;
    o.x = *reinterpret_cast<uint32_t*>(&a);
    o.y = *reinterpret_cast<uint32_t*>(&b);
    xh[i] = o;
}

// w[K,N] fp32 -> wbt[N,K] fp16 with value sign(fp16(w)) (sign(0) = 0)
__global__ void cvt_w_kernel(const float* __restrict__ w, __half* __restrict__ wbt) {
    __shared__ __half tile[32][33];
    int n0 = blockIdx.x * 32;
    int k0 = blockIdx.y * 32;
    int tx = threadIdx.x, ty = threadIdx.y;
    #pragma unroll
    for (int j = ty; j < 32; j += 8) {
        float v = w[(size_t)(k0 + j) * N_DIM + n0 + tx];
        float hf = __half2float(__float2half_rn(v));  // exact fp16 round trip
        float s = (hf > 0.f) ? 1.f : ((hf < 0.f) ? -1.f : 0.f);
        tile[j][tx] = __float2half_rn(s);
    }
    __syncthreads();
    #pragma unroll
    for (int j = ty; j < 32; j += 8) {
        wbt[(size_t)(n0 + j) * K_DIM + k0 + tx] = tile[tx][j];
    }
}

// dummy launch to keep ncu's -s window on the GEMM (worked in R4)
__global__ void prof_pad_kernel() {}

// ------------------------------ PTX helpers -------------------------------
__device__ __forceinline__ uint32_t smem_u32(const void* p) {
    uint32_t a;
    asm("{ .reg .u64 t; cvta.to.shared.u64 t, %1; cvt.u32.u64 %0, t; }"
        : "=r"(a) : "l"(p));
    return a;
}

__device__ __forceinline__ void cp_async_16(uint32_t smem_dst, const void* gmem_src) {
    asm volatile("cp.async.cg.shared.global [%0], [%1], 16;"
                 :: "r"(smem_dst), "l"(gmem_src));
}
__device__ __forceinline__ void cp_commit() {
    asm volatile("cp.async.commit_group;" ::: "memory");
}
template <int N>
__device__ __forceinline__ void cp_wait() {
    asm volatile("cp.async.wait_group %0;" :: "n"(N) : "memory");
}

__device__ __forceinline__ void ldmatrix_x4(uint32_t& r0, uint32_t& r1,
                                            uint32_t& r2, uint32_t& r3, uint32_t addr) {
    asm volatile("ldmatrix.sync.aligned.m8n8.x4.shared.b16 {%0,%1,%2,%3}, [%4];"
                 : "=r"(r0), "=r"(r1), "=r"(r2), "=r"(r3) : "r"(addr));
}

__device__ __forceinline__ void mma_16816(float* c, const uint32_t* a, const uint32_t* b) {
    asm volatile(
        "mma.sync.aligned.m16n8k16.row.col.f32.f16.f16.f32 "
        "{%0,%1,%2,%3}, {%4,%5,%6,%7}, {%8,%9}, {%0,%1,%2,%3};"
        : "+f"(c[0]), "+f"(c[1]), "+f"(c[2]), "+f"(c[3])
        : "r"(a[0]), "r"(a[1]), "r"(a[2]), "r"(a[3]), "r"(b[0]), "r"(b[1]));
}

// swizzle within a [rows][BK] fp16 tile, 128B rows: 16B chunk XOR (row & 7)
__device__ __forceinline__ uint32_t tile_off(int row, int chunk) {
    return (uint32_t)(row * 128 + ((chunk ^ (row & 7)) << 4));
}

// ------------------------------ GEMM kernel --------------------------------
__global__ void __launch_bounds__(THREADS, 1) bgemm_mma_kernel(
    const __half* __restrict__ A,   // [M,K]
    const __half* __restrict__ B,   // [N,K]
    float* __restrict__ out)
{
    extern __shared__ uint8_t smem_raw[];
    const uint32_t smem = smem_u32(smem_raw);

    const int tid  = threadIdx.x;
    const int wid  = tid >> 5;
    const int lane = tid & 31;
    const int m0 = blockIdx.x * BM;
    const int n0 = blockIdx.y * BN;

    const int warp_m = wid & 3;   // 4 warps over M: 32 rows each
    const int warp_n = wid >> 2;  // 4 warps over N: 64 cols each

    // cp.async mapping: 512 threads x 16B = 8KB/pass.
    // A: 128 rows x 8 chunks (2 passes), B: 256 rows x 8 chunks (4 passes).
    const int ld_row0  = tid >> 3;   // 0..63
    const int ld_chunk = tid & 7;    // 0..7

    auto load_stage = [&](int slot, int kt) {
        const uint32_t sA = smem + slot * STAGE_BYTES;
        const uint32_t sB = sA + A_TILE_BYTES;
        const int kcol = kt * BK + ld_chunk * 8;
        #pragma unroll
        for (int p = 0; p < 2; p++) {
            int row = ld_row0 + p * 64;
            cp_async_16(sA + tile_off(row, ld_chunk),
                        A + (size_t)(m0 + row) * K_DIM + kcol);
        }
        #pragma unroll
        for (int p = 0; p < 4; p++) {
            int row = ld_row0 + p * 64;
            cp_async_16(sB + tile_off(row, ld_chunk),
                        B + (size_t)(n0 + row) * K_DIM + kcol);
        }
        cp_commit();
    };

    const int lrow = lane & 15;    // ldmatrix row within 16
    const int lsel = lane >> 4;    // ldmatrix chunk select (0/1)

    float acc[2][8][4];
    #pragma unroll
    for (int mi = 0; mi < 2; mi++)
        #pragma unroll
        for (int ni = 0; ni < 8; ni++)
            #pragma unroll
            for (int j = 0; j < 4; j++) acc[mi][ni][j] = 0.f;

    // prologue: fill stages 0..1
    #pragma unroll
    for (int s = 0; s < STAGES - 1; s++) load_stage(s, s);

    for (int it = 0; it < NKI; it++) {
        cp_wait<STAGES - 2>();   // stage it resident
        __syncthreads();         // all warps done reading slot (it-1)%3

        if (it + STAGES - 1 < NKI)
            load_stage((it + STAGES - 1) % STAGES, it + STAGES - 1);

        const uint32_t sA = smem + (it % STAGES) * STAGE_BYTES;
        const uint32_t sB = sA + A_TILE_BYTES;

        #pragma unroll
        for (int kk = 0; kk < BK / 16; kk++) {
            const int chunk = kk * 2 + lsel;

            uint32_t a[2][4];
            #pragma unroll
            for (int mi = 0; mi < 2; mi++) {
                int row = warp_m * 32 + mi * 16 + lrow;
                ldmatrix_x4(a[mi][0], a[mi][1], a[mi][2], a[mi][3],
                            sA + tile_off(row, chunk));
            }
            uint32_t b[8][2];
            #pragma unroll
            for (int nj = 0; nj < 4; nj++) {
                int row = warp_n * 64 + nj * 16 + lrow;
                uint32_t r0, r1, r2, r3;
                ldmatrix_x4(r0, r1, r2, r3, sB + tile_off(row, chunk));
                b[nj * 2 + 0][0] = r0; b[nj * 2 + 1][0] = r1;
                b[nj * 2 + 0][1] = r2; b[nj * 2 + 1][1] = r3;
            }
            #pragma unroll
            for (int mi = 0; mi < 2; mi++)
                #pragma unroll
                for (int ni = 0; ni < 8; ni++)
                    mma_16816(acc[mi][ni], a[mi], b[ni]);
        }
    }

    // ------------------------------ epilogue -------------------------------
    const int tq = lane >> 2;       // 0..7 (row within 8)
    const int tp = lane & 3;        // col pair
    #pragma unroll
    for (int mi = 0; mi < 2; mi++) {
        #pragma unroll
        for (int ni = 0; ni < 8; ni++) {
            int r = m0 + warp_m * 32 + mi * 16 + tq;
            int c = n0 + warp_n * 64 + ni * 8 + tp * 2;
            float2 v0 = make_float2(acc[mi][ni][0], acc[mi][ni][1]);
            float2 v1 = make_float2(acc[mi][ni][2], acc[mi][ni][3]);
            *reinterpret_cast<float2*>(out + (size_t)r * N_DIM + c) = v0;
            *reinterpret_cast<float2*>(out + (size_t)(r + 8) * N_DIM + c) = v1;
        }
    }
}

// ------------------------------- host side --------------------------------
extern "C" void kernel_launch(void* const* d_in, const int* in_sizes, int n_in,
                              void* d_out, int out_size)
{
    const float* x = (const float*)d_in[0];
    const float* w = (const float*)d_in[1];
    float* out = (float*)d_out;

    void *xh_ptr = nullptr, *wbt_ptr = nullptr;
    cudaGetSymbolAddress(&xh_ptr, g_xh);
    cudaGetSymbolAddress(&wbt_ptr, g_wbt);

    {
        int n4 = (M_DIM * K_DIM) / 4;
        cvt_x_kernel<<<(n4 + 255) / 256, 256>>>((const float4*)x, (uint2*)xh_ptr, n4);
        dim3 gw(N_DIM / 32, K_DIM / 32), bw(32, 8);
        cvt_w_kernel<<<gw, bw>>>(w, (__half*)wbt_ptr);
    }

    // pad launch so ncu's "-s 5 -c 1" window lands on the GEMM
    prof_pad_kernel<<<1, 32>>>();

    cudaFuncSetAttribute(bgemm_mma_kernel,
                         cudaFuncAttributeMaxDynamicSharedMemorySize, SMEM_DYN);

    dim3 grid(M_DIM / BM, N_DIM / BN);  // (64, 16)
    bgemm_mma_kernel<<<grid, THREADS, SMEM_DYN>>>(
        (const __half*)xh_ptr, (const __half*)wbt_ptr, out);
}

// round 7
// speedup vs baseline: 1.0535x; 1.0356x over previous
#include <cuda_runtime.h>
#include <cuda_fp16.h>
#include <cstdint>

// ---------------------------------------------------------------------------
// out[8192,4096] = x[8192,4096]_fp32 @ sign(fp16(w[4096,4096]))
//
// Portable tensor-core path (target is plain sm_103): cp.async + ldmatrix +
// mma.sync.m16n8k16.f32.f16.f16.f32.
//
// R7: R6 mbarrier pipeline with the deadlock fixed: cp.async.mbarrier.arrive
// must be the .noinc variant to consume the init count (default variant
// nets zero and the full barrier never fires).
// ---------------------------------------------------------------------------

#define M_DIM 8192
#define N_DIM 4096
#define K_DIM 4096

#define BM 128
#define BN 256
#define BK 64
#define STAGES 4
#define THREADS 512
#define NKI (K_DIM / BK)   // 64

#define A_TILE_BYTES (BM * BK * 2)            // 16384
#define B_TILE_BYTES (BN * BK * 2)            // 32768
#define STAGE_BYTES  (A_TILE_BYTES + B_TILE_BYTES)   // 49152
#define SMEM_DYN     (1024 + 1024 + STAGES * STAGE_BYTES)  // 198656

// ------------------------------ scratch -----------------------------------
__device__ __align__(1024) __half g_xh[(size_t)M_DIM * K_DIM];   // 64 MB
__device__ __align__(1024) __half g_wbt[(size_t)N_DIM * K_DIM];  // 32 MB

// --------------------------- convert kernels -------------------------------
__global__ void cvt_x_kernel(const float4* __restrict__ x, uint2* __restrict__ xh, int n4) {
    int i = blockIdx.x * blockDim.x + threadIdx.x;
    if (i >= n4) return;
    float4 v = x[i];
    __half2 a = __floats2half2_rn(v.x, v.y);
    __half2 b = __floats2half2_rn(v.z, v.w);
    uint2 o;
    o.x = *reinterpret_cast<uint32_t*>(&a);
    o.y = *reinterpret_cast<uint32_t*>(&b);
    xh[i] = o;
}

// w[K,N] fp32 -> wbt[N,K] fp16 with value sign(fp16(w)) (sign(0) = 0)
__global__ void cvt_w_kernel(const float* __restrict__ w, __half* __restrict__ wbt) {
    __shared__ __half tile[32][33];
    int n0 = blockIdx.x * 32;
    int k0 = blockIdx.y * 32;
    int tx = threadIdx.x, ty = threadIdx.y;
    #pragma unroll
    for (int j = ty; j < 32; j += 8) {
        float v = w[(size_t)(k0 + j) * N_DIM + n0 + tx];
        float hf = __half2float(__float2half_rn(v));  // exact fp16 round trip
        float s = (hf > 0.f) ? 1.f : ((hf < 0.f) ? -1.f : 0.f);
        tile[j][tx] = __float2half_rn(s);
    }
    __syncthreads();
    #pragma unroll
    for (int j = ty; j < 32; j += 8) {
        wbt[(size_t)(n0 + j) * K_DIM + k0 + tx] = tile[tx][j];
    }
}

// dummy launch to keep ncu's -s window on the GEMM (worked in R4/R5)
__global__ void prof_pad_kernel() {}

// ------------------------------ PTX helpers -------------------------------
__device__ __forceinline__ uint32_t smem_u32(const void* p) {
    uint32_t a;
    asm("{ .reg .u64 t; cvta.to.shared.u64 t, %1; cvt.u32.u64 %0, t; }"
        : "=r"(a) : "l"(p));
    return a;
}

__device__ __forceinline__ void cp_async_16(uint32_t smem_dst, const void* gmem_src) {
    asm volatile("cp.async.cg.shared.global [%0], [%1], 16;"
                 :: "r"(smem_dst), "l"(gmem_src));
}

#define MBARRIER_INIT(addr, count) \
    asm volatile("mbarrier.init.shared.b64 [%0], %1;" \
                 :: "r"((uint32_t)(addr)), "r"((uint32_t)(count)) : "memory")

#define MBARRIER_ARRIVE(addr) \
    asm volatile("mbarrier.arrive.shared.b64 _, [%0];" \
                 :: "r"((uint32_t)(addr)) : "memory")

// arrive (consuming one init-count slot) once this thread's prior cp.asyncs
// have completed. MUST be .noinc: the default variant increments the pending
// count at issue and nets zero against the init count -> barrier never fires.
#define CPASYNC_MBAR_ARRIVE_NOINC(addr) \
    asm volatile("cp.async.mbarrier.arrive.noinc.shared.b64 [%0];" \
                 :: "r"((uint32_t)(addr)) : "memory")

#define MBARRIER_WAIT_PARITY(mbar_smem_addr, phase_parity) do { \
    uint32_t _mbar = (uint32_t)(mbar_smem_addr); \
    uint32_t _parity = (uint32_t)(phase_parity); \
    uint32_t _done; \
    asm volatile( \
        "{\n\t.reg .pred p;\n\t" \
        "mbarrier.try_wait.parity.acquire.cta.shared::cta.b64 p, [%1], %2;\n\t" \
        "selp.b32 %0, 1, 0, p;\n\t}" \
        : "=r"(_done) : "r"(_mbar), "r"(_parity) : "memory"); \
    if (!_done) { \
        asm volatile( \
            "{\n\t.reg .pred P1;\n\t" \
            "WAIT_LOOP_%=:\n\t" \
            "mbarrier.try_wait.parity.acquire.cta.shared::cta.b64 P1, [%0], %1, 0x989680;\n\t" \
            "@P1 bra.uni WAIT_DONE_%=;\n\t" \
            "bra.uni WAIT_LOOP_%=;\n\t" \
            "WAIT_DONE_%=:\n\t}" \
            :: "r"(_mbar), "r"(_parity) : "memory"); \
    } \
} while(0)

__device__ __forceinline__ void ldmatrix_x4(uint32_t& r0, uint32_t& r1,
                                            uint32_t& r2, uint32_t& r3, uint32_t addr) {
    asm volatile("ldmatrix.sync.aligned.m8n8.x4.shared.b16 {%0,%1,%2,%3}, [%4];"
                 : "=r"(r0), "=r"(r1), "=r"(r2), "=r"(r3) : "r"(addr));
}

__device__ __forceinline__ void mma_16816(float* c, const uint32_t* a, const uint32_t* b) {
    asm volatile(
        "mma.sync.aligned.m16n8k16.row.col.f32.f16.f16.f32 "
        "{%0,%1,%2,%3}, {%4,%5,%6,%7}, {%8,%9}, {%0,%1,%2,%3};"
        : "+f"(c[0]), "+f"(c[1]), "+f"(c[2]), "+f"(c[3])
        : "r"(a[0]), "r"(a[1]), "r"(a[2]), "r"(a[3]), "r"(b[0]), "r"(b[1]));
}

// swizzle within a [rows][BK] fp16 tile, 128B rows: 16B chunk XOR (row & 7)
__device__ __forceinline__ uint32_t tile_off(int row, int chunk) {
    return (uint32_t)(row * 128 + ((chunk ^ (row & 7)) << 4));
}

// ------------------------------ GEMM kernel --------------------------------
__global__ void __launch_bounds__(THREADS, 1) bgemm_mma_kernel(
    const __half* __restrict__ A,   // [M,K]
    const __half* __restrict__ B,   // [N,K]
    float* __restrict__ out)
{
    extern __shared__ uint8_t smem_raw[];
    uint32_t raw = smem_u32(smem_raw);
    const uint32_t hdr   = (raw + 1023u) & ~1023u;  // barriers live here
    const uint32_t tiles = hdr + 1024u;             // 1024-aligned stage base

    #define FULL_BAR(s)  (hdr + (uint32_t)(s) * 8u)
    #define EMPTY_BAR(s) (hdr + 64u + (uint32_t)(s) * 8u)

    const int tid  = threadIdx.x;
    const int wid  = tid >> 5;
    const int lane = tid & 31;
    const int m0 = blockIdx.x * BM;
    const int n0 = blockIdx.y * BN;

    const int warp_m = wid & 3;   // 4 warps over M: 32 rows each
    const int warp_n = wid >> 2;  // 4 warps over N: 64 cols each

    // cp.async mapping: 512 threads x 16B = 8KB/pass
    const int ld_row0  = tid >> 3;   // 0..63
    const int ld_chunk = tid & 7;    // 0..7

    auto load_stage = [&](int slot, int kt) {
        const uint32_t sA = tiles + slot * STAGE_BYTES;
        const uint32_t sB = sA + A_TILE_BYTES;
        const int kcol = kt * BK + ld_chunk * 8;
        #pragma unroll
        for (int p = 0; p < 2; p++) {
            int row = ld_row0 + p * 64;
            cp_async_16(sA + tile_off(row, ld_chunk),
                        A + (size_t)(m0 + row) * K_DIM + kcol);
        }
        #pragma unroll
        for (int p = 0; p < 4; p++) {
            int row = ld_row0 + p * 64;
            cp_async_16(sB + tile_off(row, ld_chunk),
                        B + (size_t)(n0 + row) * K_DIM + kcol);
        }
        CPASYNC_MBAR_ARRIVE_NOINC(FULL_BAR(slot));
    };

    if (tid == 0) {
        #pragma unroll
        for (int s = 0; s < STAGES; s++) {
            MBARRIER_INIT(FULL_BAR(s), THREADS);
            MBARRIER_INIT(EMPTY_BAR(s), THREADS);
        }
        asm volatile("fence.proxy.async.shared::cta;" ::: "memory");
    }
    __syncthreads();

    const int lrow = lane & 15;    // ldmatrix row within 16
    const int lsel = lane >> 4;    // ldmatrix chunk select (0/1)

    // hoisted swizzled LDSM offsets (relative to stage A/B base);
    // per-kk address = base ^ (kk << 5)   (swizzle field is XOR-separable)
    uint32_t a_off[2], b_off[4];
    #pragma unroll
    for (int mi = 0; mi < 2; mi++) {
        int row = warp_m * 32 + mi * 16 + lrow;
        a_off[mi] = tile_off(row, lsel);
    }
    #pragma unroll
    for (int nj = 0; nj < 4; nj++) {
        int row = warp_n * 64 + nj * 16 + lrow;
        b_off[nj] = tile_off(row, lsel);
    }

    float acc[2][8][4];
    #pragma unroll
    for (int mi = 0; mi < 2; mi++)
        #pragma unroll
        for (int ni = 0; ni < 8; ni++)
            #pragma unroll
            for (int j = 0; j < 4; j++) acc[mi][ni][j] = 0.f;

    // prologue: fill stages 0..2 (empty-wait parity 1 passes immediately:
    // current phase parity is 0, wait passes when parity != P)
    #pragma unroll
    for (int s = 0; s < STAGES - 1; s++) {
        MBARRIER_WAIT_PARITY(EMPTY_BAR(s), 1);
        load_stage(s, s);
    }

    for (int it = 0; it < NKI; it++) {
        const int s = it & 3;
        const uint32_t sA = tiles + s * STAGE_BYTES;
        const uint32_t sB = sA + A_TILE_BYTES;

        // consumer: wait for stage it (full round r=it>>2, parity r&1)
        MBARRIER_WAIT_PARITY(FULL_BAR(s), (it >> 2) & 1);

        #pragma unroll
        for (int kk = 0; kk < BK / 16; kk++) {
            const uint32_t kx = (uint32_t)kk << 5;

            uint32_t a[2][4];
            #pragma unroll
            for (int mi = 0; mi < 2; mi++)
                ldmatrix_x4(a[mi][0], a[mi][1], a[mi][2], a[mi][3],
                            (sA + a_off[mi]) ^ kx);
            uint32_t b[8][2];
            #pragma unroll
            for (int nj = 0; nj < 4; nj++) {
                uint32_t r0, r1, r2, r3;
                ldmatrix_x4(r0, r1, r2, r3, (sB + b_off[nj]) ^ kx);
                b[nj * 2 + 0][0] = r0; b[nj * 2 + 1][0] = r1;
                b[nj * 2 + 0][1] = r2; b[nj * 2 + 1][1] = r3;
            }

            // release the stage right after our LAST smem read of it,
            // before the MMAs drain (arrive.release orders the reads)
            if (kk == BK / 16 - 1) MBARRIER_ARRIVE(EMPTY_BAR(s));

            #pragma unroll
            for (int mi = 0; mi < 2; mi++)
                #pragma unroll
                for (int ni = 0; ni < 8; ni++)
                    mma_16816(acc[mi][ni], a[mi], b[ni]);
        }

        // producer: refill stage it+3 (empty round r=kt>>2, parity (r&1)^1)
        const int kt = it + STAGES - 1;
        if (kt < NKI) {
            const int ps = kt & 3;
            MBARRIER_WAIT_PARITY(EMPTY_BAR(ps), ((kt >> 2) & 1) ^ 1);
            load_stage(ps, kt);
        }
    }

    // ------------------------------ epilogue -------------------------------
    const int tq = lane >> 2;       // 0..7 (row within 8)
    const int tp = lane & 3;        // col pair
    #pragma unroll
    for (int mi = 0; mi < 2; mi++) {
        #pragma unroll
        for (int ni = 0; ni < 8; ni++) {
            int r = m0 + warp_m * 32 + mi * 16 + tq;
            int c = n0 + warp_n * 64 + ni * 8 + tp * 2;
            float2 v0 = make_float2(acc[mi][ni][0], acc[mi][ni][1]);
            float2 v1 = make_float2(acc[mi][ni][2], acc[mi][ni][3]);
            *reinterpret_cast<float2*>(out + (size_t)r * N_DIM + c) = v0;
            *reinterpret_cast<float2*>(out + (size_t)(r + 8) * N_DIM + c) = v1;
        }
    }
}

// ------------------------------- host side --------------------------------
extern "C" void kernel_launch(void* const* d_in, const int* in_sizes, int n_in,
                              void* d_out, int out_size)
{
    const float* x = (const float*)d_in[0];
    const float* w = (const float*)d_in[1];
    float* out = (float*)d_out;

    void *xh_ptr = nullptr, *wbt_ptr = nullptr;
    cudaGetSymbolAddress(&xh_ptr, g_xh);
    cudaGetSymbolAddress(&wbt_ptr, g_wbt);

    {
        int n4 = (M_DIM * K_DIM) / 4;
        cvt_x_kernel<<<(n4 + 255) / 256, 256>>>((const float4*)x, (uint2*)xh_ptr, n4);
        dim3 gw(N_DIM / 32, K_DIM / 32), bw(32, 8);
        cvt_w_kernel<<<gw, bw>>>(w, (__half*)wbt_ptr);
    }

    // pad launch so ncu's "-s 5 -c 1" window lands on the GEMM
    prof_pad_kernel<<<1, 32>>>();

    cudaFuncSetAttribute(bgemm_mma_kernel,
                         cudaFuncAttributeMaxDynamicSharedMemorySize, SMEM_DYN);

    dim3 grid(M_DIM / BM, N_DIM / BN);  // (64, 16)
    bgemm_mma_kernel<<<grid, THREADS, SMEM_DYN>>>(
        (const __half*)xh_ptr, (const __half*)wbt_ptr, out);
}